// round 1
// baseline (speedup 1.0000x reference)
#include <cuda_runtime.h>

#define NN 20000
#define NE 320000
#define NG 256
#define NA 23
#define NB 7
#define M0 64
#define M1 24
#define M2 16
#define NUV (NA*NB)      // 161
#define MB (M1+M2)       // 40
#define NFEAT 216        // 64 + 24*3 + 16*5
#define OFF1 64
#define OFF2 136

// scratch (no allocations allowed)
__device__ float g_nfeat[(size_t)NN * NFEAT];   // per-node features n0|n1|n2
__device__ float g_nodeout[NN];

// constants
#define A1  0.078811041f   // 1/sqrt(23*7)
#define C0  0.047245559f   // 1/sqrt(64*7)
#define C1  0.044543540f   // 1/sqrt(24*7*3)
#define C2  0.042257713f   // 1/sqrt(16*7*5)
#define S3  1.7320508075688772f
#define S5  2.23606797749979f
#define S15 3.872983346207417f

__global__ void k_zero(float* __restrict__ out) {
    long long i = (long long)blockIdx.x * blockDim.x + threadIdx.x;
    long long stride = (long long)gridDim.x * blockDim.x;
    for (long long j = i; j < (long long)NN * NFEAT; j += stride) g_nfeat[j] = 0.f;
    for (long long j = i; j < NN; j += stride) g_nodeout[j] = 0.f;
    for (long long j = i; j < NG; j += stride) out[j] = 0.f;
}

// -------- pass 1a: n0 (64 features) ----------------------------------------
__global__ void __launch_bounds__(128) k_pass1a(
    const float* __restrict__ x, const float* __restrict__ ea,
    const int* __restrict__ ei, const float* __restrict__ W1)
{
    __shared__ float Ws[NUV * M0];   // 41216 B, W1 layout matches exactly
    for (int i = threadIdx.x; i < NUV * M0; i += blockDim.x) Ws[i] = W1[i];
    __syncthreads();

    int e = blockIdx.x * blockDim.x + threadIdx.x;
    if (e >= NE) return;
    int src = ei[e];
    int dst = ei[NE + e];

    float eav[NB];
#pragma unroll
    for (int v = 0; v < NB; v++) eav[v] = ea[e * NB + v];

    float acc[M0];
#pragma unroll
    for (int w = 0; w < M0; w++) acc[w] = 0.f;

    const float* xrow = x + (long long)src * NA;
#pragma unroll 1
    for (int u = 0; u < NA; u++) {
        float xu = xrow[u];
        const float* wrow = &Ws[u * NB * M0];
#pragma unroll
        for (int v = 0; v < NB; v++) {
            float pv = xu * eav[v];
            const float* wp = wrow + v * M0;
#pragma unroll
            for (int w = 0; w < M0; w++) acc[w] = fmaf(pv, wp[w], acc[w]);
        }
    }

    float* nf = g_nfeat + (long long)dst * NFEAT;
#pragma unroll
    for (int w = 0; w < M0; w++) atomicAdd(nf + w, A1 * acc[w]);
}

// -------- pass 1b: n1 (24x3) and n2 (16x5) ----------------------------------
__global__ void __launch_bounds__(128) k_pass1b(
    const float* __restrict__ pos, const float* __restrict__ x,
    const float* __restrict__ ea, const int* __restrict__ ei,
    const float* __restrict__ W2, const float* __restrict__ W3)
{
    __shared__ float Ws[NUV * MB];   // 25760 B, cols 0..23 = W2, 24..39 = W3
    for (int i = threadIdx.x; i < NUV * M1; i += blockDim.x) {
        int p = i / M1, w = i - p * M1;
        Ws[p * MB + w] = W2[i];
    }
    for (int i = threadIdx.x; i < NUV * M2; i += blockDim.x) {
        int p = i / M2, w = i - p * M2;
        Ws[p * MB + M1 + w] = W3[i];
    }
    __syncthreads();

    int e = blockIdx.x * blockDim.x + threadIdx.x;
    if (e >= NE) return;
    int src = ei[e];
    int dst = ei[NE + e];

    float px = pos[src * 3 + 0] - pos[dst * 3 + 0];
    float py = pos[src * 3 + 1] - pos[dst * 3 + 1];
    float pz = pos[src * 3 + 2] - pos[dst * 3 + 2];
    float sh1x = S3 * px, sh1y = S3 * py, sh1z = S3 * pz;
    float r2 = px * px + py * py + pz * pz;
    float sh2_0 = S15 * px * py;
    float sh2_1 = S15 * py * pz;
    float sh2_2 = 0.5f * S5 * (3.f * pz * pz - r2);
    float sh2_3 = S15 * px * pz;
    float sh2_4 = 0.5f * S15 * (px * px - py * py);

    float eav[NB];
#pragma unroll
    for (int v = 0; v < NB; v++) eav[v] = ea[e * NB + v];

    float acc[MB];
#pragma unroll
    for (int w = 0; w < MB; w++) acc[w] = 0.f;

    const float* xrow = x + (long long)src * NA;
#pragma unroll 1
    for (int u = 0; u < NA; u++) {
        float xu = xrow[u];
        const float* wrow = &Ws[u * NB * MB];
#pragma unroll
        for (int v = 0; v < NB; v++) {
            float pv = xu * eav[v];
            const float* wp = wrow + v * MB;
#pragma unroll
            for (int w = 0; w < MB; w++) acc[w] = fmaf(pv, wp[w], acc[w]);
        }
    }

    float* nf = g_nfeat + (long long)dst * NFEAT;
#pragma unroll
    for (int j = 0; j < M1; j++) {
        float h = A1 * acc[j];
        atomicAdd(nf + OFF1 + j * 3 + 0, h * sh1x);
        atomicAdd(nf + OFF1 + j * 3 + 1, h * sh1y);
        atomicAdd(nf + OFF1 + j * 3 + 2, h * sh1z);
    }
#pragma unroll
    for (int j = 0; j < M2; j++) {
        float h = A1 * acc[M1 + j];
        atomicAdd(nf + OFF2 + j * 5 + 0, h * sh2_0);
        atomicAdd(nf + OFF2 + j * 5 + 1, h * sh2_1);
        atomicAdd(nf + OFF2 + j * 5 + 2, h * sh2_2);
        atomicAdd(nf + OFF2 + j * 5 + 3, h * sh2_3);
        atomicAdd(nf + OFF2 + j * 5 + 4, h * sh2_4);
    }
}

// -------- pass 2: per-edge invariant g, scatter to nodes --------------------
__global__ void __launch_bounds__(128) k_pass2(
    const float* __restrict__ pos, const float* __restrict__ ea,
    const int* __restrict__ ei, const float* __restrict__ V1,
    const float* __restrict__ V2, const float* __restrict__ V3)
{
    __shared__ float Vs[(M0 + M1 + M2) * NB];   // 728 floats
    for (int i = threadIdx.x; i < (M0 + M1 + M2) * NB; i += blockDim.x) {
        float v;
        if (i < M0 * NB)            v = V1[i];
        else if (i < (M0 + M1) * NB) v = V2[i - M0 * NB];
        else                         v = V3[i - (M0 + M1) * NB];
        Vs[i] = v;
    }
    __syncthreads();

    int e = blockIdx.x * blockDim.x + threadIdx.x;
    if (e >= NE) return;
    int src = ei[e];
    int dst = ei[NE + e];

    float px = pos[src * 3 + 0] - pos[dst * 3 + 0];
    float py = pos[src * 3 + 1] - pos[dst * 3 + 1];
    float pz = pos[src * 3 + 2] - pos[dst * 3 + 2];
    float sh1x = S3 * px, sh1y = S3 * py, sh1z = S3 * pz;
    float r2 = px * px + py * py + pz * pz;
    float sh2_0 = S15 * px * py;
    float sh2_1 = S15 * py * pz;
    float sh2_2 = 0.5f * S5 * (3.f * pz * pz - r2);
    float sh2_3 = S15 * px * pz;
    float sh2_4 = 0.5f * S15 * (px * px - py * py);

    float eav[NB];
#pragma unroll
    for (int v = 0; v < NB; v++) eav[v] = ea[e * NB + v];

    const float* nf = g_nfeat + (long long)src * NFEAT;

    float g1 = 0.f;
#pragma unroll 1
    for (int u = 0; u < M0; u++) {
        float qu = 0.f;
#pragma unroll
        for (int v = 0; v < NB; v++) qu = fmaf(eav[v], Vs[u * NB + v], qu);
        g1 = fmaf(nf[u], qu, g1);
    }

    float g2 = 0.f;
#pragma unroll 1
    for (int u = 0; u < M1; u++) {
        const float* p = nf + OFF1 + u * 3;
        float r = p[0] * sh1x + p[1] * sh1y + p[2] * sh1z;
        float qu = 0.f;
#pragma unroll
        for (int v = 0; v < NB; v++) qu = fmaf(eav[v], Vs[M0 * NB + u * NB + v], qu);
        g2 = fmaf(r, qu, g2);
    }

    float g3 = 0.f;
#pragma unroll 1
    for (int u = 0; u < M2; u++) {
        const float* p = nf + OFF2 + u * 5;
        float r = p[0] * sh2_0 + p[1] * sh2_1 + p[2] * sh2_2 + p[3] * sh2_3 + p[4] * sh2_4;
        float qu = 0.f;
#pragma unroll
        for (int v = 0; v < NB; v++) qu = fmaf(eav[v], Vs[(M0 + M1) * NB + u * NB + v], qu);
        g3 = fmaf(r, qu, g3);
    }

    float g = C0 * g1 + C1 * g2 + C2 * g3;
    atomicAdd(&g_nodeout[dst], g);
}

// -------- pass 3: node -> graph ---------------------------------------------
__global__ void k_pass3(const int* __restrict__ batch, float* __restrict__ out) {
    int i = blockIdx.x * blockDim.x + threadIdx.x;
    if (i < NN) atomicAdd(&out[batch[i]], g_nodeout[i]);
}

extern "C" void kernel_launch(void* const* d_in, const int* in_sizes, int n_in,
                              void* d_out, int out_size) {
    const float* pos   = (const float*)d_in[0];
    const float* x     = (const float*)d_in[1];
    const float* ea    = (const float*)d_in[2];
    const int*   ei    = (const int*)d_in[3];
    const int*   batch = (const int*)d_in[4];
    const float* W1    = (const float*)d_in[5];
    const float* W2    = (const float*)d_in[6];
    const float* W3    = (const float*)d_in[7];
    const float* V1    = (const float*)d_in[8];
    const float* V2    = (const float*)d_in[9];
    const float* V3    = (const float*)d_in[10];
    float* out = (float*)d_out;

    k_zero<<<4224, 1024>>>(out);
    k_pass1a<<<NE / 128, 128>>>(x, ea, ei, W1);
    k_pass1b<<<NE / 128, 128>>>(pos, x, ea, ei, W2, W3);
    k_pass2<<<NE / 128, 128>>>(pos, ea, ei, V1, V2, V3);
    k_pass3<<<(NN + 255) / 256, 256>>>(batch, out);
}

// round 2
// speedup vs baseline: 2.1559x; 2.1559x over previous
#include <cuda_runtime.h>

#define NN 20000
#define NE 320000
#define NG 256
#define NA 23
#define NB 7
#define M0 64
#define M1 24
#define M2 16
#define NUV (NA*NB)      // 161
#define MB (M1+M2)       // 40
#define NFEAT 216        // 64 + 24*3 + 16*5
#define OFF1 64
#define OFF2 136
#define MDIM 64          // per-node reduced feature (63 + pad)

__device__ float g_nfeat[(size_t)NN * NFEAT];
__device__ float g_m[(size_t)NN * MDIM];
__device__ float g_nodeout[NN];

#define A1  0.078811041f   // 1/sqrt(23*7)
#define C0  0.047245559f   // 1/sqrt(64*7)
#define C1  0.044543540f   // 1/sqrt(24*7*3)
#define C2  0.042257713f   // 1/sqrt(16*7*5)
#define S3  1.7320508075688772f
#define S5  2.23606797749979f
#define S15 3.872983346207417f

#define FMA2(d,a,b,c) asm("fma.rn.f32x2 %0, %1, %2, %3;" : "=l"(d) : "l"(a), "l"(b), "l"(c))
#define PACK2(d,lo,hi) asm("mov.b64 %0, {%1,%2};" : "=l"(d) : "f"(lo), "f"(hi))
#define UNPACK2(lo,hi,s) asm("mov.b64 {%0,%1}, %2;" : "=f"(lo), "=f"(hi) : "l"(s))
#define RED4(p,a,b,c,d) asm volatile("red.global.add.v4.f32 [%0], {%1,%2,%3,%4};" :: "l"(p), "f"(a), "f"(b), "f"(c), "f"(d) : "memory")

__global__ void k_zero(float* __restrict__ out) {
    long long i = (long long)blockIdx.x * blockDim.x + threadIdx.x;
    long long stride = (long long)gridDim.x * blockDim.x;
    for (long long j = i; j < (long long)NN * NFEAT; j += stride) g_nfeat[j] = 0.f;
    for (long long j = i; j < NN; j += stride) g_nodeout[j] = 0.f;
    for (long long j = i; j < NG; j += stride) out[j] = 0.f;
}

// -------- pass 1a: n0 (64 features), 2 edges per thread, f32x2 FMA ----------
__global__ void __launch_bounds__(128) k_pass1a(
    const float* __restrict__ x, const float* __restrict__ ea,
    const int* __restrict__ ei, const float* __restrict__ W1)
{
    __shared__ float Ws[NUV * M0];   // 41216 B, same layout as W1
    for (int i = threadIdx.x; i < NUV * M0; i += blockDim.x) Ws[i] = W1[i];
    __syncthreads();

    int e0 = blockIdx.x * 256 + threadIdx.x;
    int e1 = e0 + 128;
    int s0 = ei[e0], s1 = ei[e1];
    int d0 = ei[NE + e0], d1 = ei[NE + e1];

    float ea0[NB], ea1[NB];
#pragma unroll
    for (int v = 0; v < NB; v++) { ea0[v] = ea[e0 * NB + v]; ea1[v] = ea[e1 * NB + v]; }

    unsigned long long acc0[32], acc1[32];
#pragma unroll
    for (int i = 0; i < 32; i++) { acc0[i] = 0ull; acc1[i] = 0ull; }

    const float* xr0 = x + (long long)s0 * NA;
    const float* xr1 = x + (long long)s1 * NA;

#pragma unroll 1
    for (int u = 0; u < NA; u++) {
        float xu0 = __ldg(xr0 + u);
        float xu1 = __ldg(xr1 + u);
        const ulonglong2* wrow = (const ulonglong2*)&Ws[u * NB * M0];
#pragma unroll
        for (int v = 0; v < NB; v++) {
            float p0 = xu0 * ea0[v];
            float p1 = xu1 * ea1[v];
            unsigned long long P0, P1;
            PACK2(P0, p0, p0);
            PACK2(P1, p1, p1);
            const ulonglong2* wp = wrow + v * 16;   // 64 floats = 16 ull2
#pragma unroll
            for (int q = 0; q < 16; q++) {
                ulonglong2 wv = wp[q];
                FMA2(acc0[2*q],   P0, wv.x, acc0[2*q]);
                FMA2(acc0[2*q+1], P0, wv.y, acc0[2*q+1]);
                FMA2(acc1[2*q],   P1, wv.x, acc1[2*q]);
                FMA2(acc1[2*q+1], P1, wv.y, acc1[2*q+1]);
            }
        }
    }

    float* nf0 = g_nfeat + (long long)d0 * NFEAT;
    float* nf1 = g_nfeat + (long long)d1 * NFEAT;
#pragma unroll
    for (int i = 0; i < 16; i++) {
        float a, b, c, d;
        UNPACK2(a, b, acc0[2*i]);
        UNPACK2(c, d, acc0[2*i+1]);
        RED4(nf0 + i*4, A1*a, A1*b, A1*c, A1*d);
    }
#pragma unroll
    for (int i = 0; i < 16; i++) {
        float a, b, c, d;
        UNPACK2(a, b, acc1[2*i]);
        UNPACK2(c, d, acc1[2*i+1]);
        RED4(nf1 + i*4, A1*a, A1*b, A1*c, A1*d);
    }
}

// -------- pass 1b: n1 (24x3) and n2 (16x5), 2 edges per thread --------------
__global__ void __launch_bounds__(128) k_pass1b(
    const float* __restrict__ pos, const float* __restrict__ x,
    const float* __restrict__ ea, const int* __restrict__ ei,
    const float* __restrict__ W2, const float* __restrict__ W3)
{
    __shared__ float Ws[NUV * MB];   // cols 0..23 = W2, 24..39 = W3
    for (int i = threadIdx.x; i < NUV * M1; i += blockDim.x) {
        int p = i / M1, w = i - p * M1;
        Ws[p * MB + w] = W2[i];
    }
    for (int i = threadIdx.x; i < NUV * M2; i += blockDim.x) {
        int p = i / M2, w = i - p * M2;
        Ws[p * MB + M1 + w] = W3[i];
    }
    __syncthreads();

    int e0 = blockIdx.x * 256 + threadIdx.x;
    int e1 = e0 + 128;
    int s0 = ei[e0], s1 = ei[e1];
    int d0 = ei[NE + e0], d1 = ei[NE + e1];

    float ea0[NB], ea1[NB];
#pragma unroll
    for (int v = 0; v < NB; v++) { ea0[v] = ea[e0 * NB + v]; ea1[v] = ea[e1 * NB + v]; }

    unsigned long long acc0[20], acc1[20];
#pragma unroll
    for (int i = 0; i < 20; i++) { acc0[i] = 0ull; acc1[i] = 0ull; }

    const float* xr0 = x + (long long)s0 * NA;
    const float* xr1 = x + (long long)s1 * NA;

#pragma unroll 1
    for (int u = 0; u < NA; u++) {
        float xu0 = __ldg(xr0 + u);
        float xu1 = __ldg(xr1 + u);
        const ulonglong2* wrow = (const ulonglong2*)&Ws[u * NB * MB];
#pragma unroll
        for (int v = 0; v < NB; v++) {
            float p0 = xu0 * ea0[v];
            float p1 = xu1 * ea1[v];
            unsigned long long P0, P1;
            PACK2(P0, p0, p0);
            PACK2(P1, p1, p1);
            const ulonglong2* wp = wrow + v * 10;   // 40 floats = 10 ull2
#pragma unroll
            for (int q = 0; q < 10; q++) {
                ulonglong2 wv = wp[q];
                FMA2(acc0[2*q],   P0, wv.x, acc0[2*q]);
                FMA2(acc0[2*q+1], P0, wv.y, acc0[2*q+1]);
                FMA2(acc1[2*q],   P1, wv.x, acc1[2*q]);
                FMA2(acc1[2*q+1], P1, wv.y, acc1[2*q+1]);
            }
        }
    }

    // spherical harmonics + emission, per edge
#pragma unroll
    for (int half = 0; half < 2; half++) {
        int s = half ? s1 : s0;
        int d = half ? d1 : d0;
        unsigned long long* acc = half ? acc1 : acc0;

        float px = pos[s*3+0] - pos[d*3+0];
        float py = pos[s*3+1] - pos[d*3+1];
        float pz = pos[s*3+2] - pos[d*3+2];
        float shv[3] = { S3*px, S3*py, S3*pz };
        float r2 = px*px + py*py + pz*pz;
        float sh2v[5] = { S15*px*py, S15*py*pz, 0.5f*S5*(3.f*pz*pz - r2),
                          S15*px*pz, 0.5f*S15*(px*px - py*py) };

        float h[MB];
#pragma unroll
        for (int i = 0; i < 20; i++) {
            float lo, hi;
            UNPACK2(lo, hi, acc[i]);
            h[2*i] = A1 * lo;
            h[2*i+1] = A1 * hi;
        }

        float* nf = g_nfeat + (long long)d * NFEAT;
        // l=1 block: 72 floats, val[k] = h[k/3]*shv[k%3]
#pragma unroll
        for (int q = 0; q < 18; q++) {
            float v0 = h[(4*q+0)/3] * shv[(4*q+0)%3];
            float v1 = h[(4*q+1)/3] * shv[(4*q+1)%3];
            float v2 = h[(4*q+2)/3] * shv[(4*q+2)%3];
            float v3 = h[(4*q+3)/3] * shv[(4*q+3)%3];
            RED4(nf + OFF1 + 4*q, v0, v1, v2, v3);
        }
        // l=2 block: 80 floats, val[k] = h[24+k/5]*sh2v[k%5]
#pragma unroll
        for (int q = 0; q < 20; q++) {
            float v0 = h[M1 + (4*q+0)/5] * sh2v[(4*q+0)%5];
            float v1 = h[M1 + (4*q+1)/5] * sh2v[(4*q+1)%5];
            float v2 = h[M1 + (4*q+2)/5] * sh2v[(4*q+2)%5];
            float v3 = h[M1 + (4*q+3)/5] * sh2v[(4*q+3)%5];
            RED4(nf + OFF2 + 4*q, v0, v1, v2, v3);
        }
    }
}

// -------- per-node V contraction: m[node, 64] --------------------------------
// k<7:      m0[v]  = C0 * sum_u  nf[u]          * V1[u,v]
// 7<=k<28:  m1[v,m]= C1 * sum_u  nf[64+u*3+m]   * V2[u,v]
// 28<=k<63: m2[v,m]= C2 * sum_u  nf[136+u*5+m]  * V3[u,v]
__global__ void __launch_bounds__(256) k_nodeV(
    const float* __restrict__ V1, const float* __restrict__ V2,
    const float* __restrict__ V3)
{
    __shared__ float Vs[(M0 + M1 + M2) * NB];
    for (int i = threadIdx.x; i < (M0 + M1 + M2) * NB; i += blockDim.x) {
        float v;
        if (i < M0 * NB)             v = V1[i];
        else if (i < (M0 + M1) * NB) v = V2[i - M0 * NB];
        else                         v = V3[i - (M0 + M1) * NB];
        Vs[i] = v;
    }
    __syncthreads();

    int gid = blockIdx.x * 256 + threadIdx.x;
    int node = gid >> 6;
    int k = gid & 63;
    if (node >= NN) return;
    const float* nf = g_nfeat + (long long)node * NFEAT;

    float r = 0.f;
    if (k < 7) {
        int v = k;
        for (int u = 0; u < M0; u++) r = fmaf(nf[u], Vs[u*NB + v], r);
        r *= C0;
    } else if (k < 28) {
        int t = k - 7; int v = t / 3; int m = t - 3*v;
        for (int u = 0; u < M1; u++) r = fmaf(nf[OFF1 + u*3 + m], Vs[M0*NB + u*NB + v], r);
        r *= C1;
    } else if (k < 63) {
        int t = k - 28; int v = t / 5; int m = t - 5*v;
        for (int u = 0; u < M2; u++) r = fmaf(nf[OFF2 + u*5 + m], Vs[(M0+M1)*NB + u*NB + v], r);
        r *= C2;
    }
    g_m[(long long)node * MDIM + k] = r;
}

// -------- pass 2: per-edge invariant from reduced features ------------------
__global__ void __launch_bounds__(128) k_pass2(
    const float* __restrict__ pos, const float* __restrict__ ea,
    const int* __restrict__ ei)
{
    int e = blockIdx.x * blockDim.x + threadIdx.x;
    if (e >= NE) return;
    int src = ei[e];
    int dst = ei[NE + e];

    float px = pos[src*3+0] - pos[dst*3+0];
    float py = pos[src*3+1] - pos[dst*3+1];
    float pz = pos[src*3+2] - pos[dst*3+2];
    float sh1x = S3*px, sh1y = S3*py, sh1z = S3*pz;
    float r2 = px*px + py*py + pz*pz;
    float sh2_0 = S15*px*py;
    float sh2_1 = S15*py*pz;
    float sh2_2 = 0.5f*S5*(3.f*pz*pz - r2);
    float sh2_3 = S15*px*pz;
    float sh2_4 = 0.5f*S15*(px*px - py*py);

    float eav[NB];
#pragma unroll
    for (int v = 0; v < NB; v++) eav[v] = ea[e * NB + v];

    float mreg[64];
    const float4* mp = (const float4*)(g_m + (long long)src * MDIM);
#pragma unroll
    for (int i = 0; i < 16; i++) ((float4*)mreg)[i] = __ldg(mp + i);

    float g = 0.f;
#pragma unroll
    for (int v = 0; v < NB; v++) {
        const float* m1v = mreg + 7 + v*3;
        const float* m2v = mreg + 28 + v*5;
        float t = mreg[v];
        t = fmaf(sh1x, m1v[0], t);
        t = fmaf(sh1y, m1v[1], t);
        t = fmaf(sh1z, m1v[2], t);
        t = fmaf(sh2_0, m2v[0], t);
        t = fmaf(sh2_1, m2v[1], t);
        t = fmaf(sh2_2, m2v[2], t);
        t = fmaf(sh2_3, m2v[3], t);
        t = fmaf(sh2_4, m2v[4], t);
        g = fmaf(eav[v], t, g);
    }
    atomicAdd(&g_nodeout[dst], g);
}

// -------- pass 3: node -> graph ---------------------------------------------
__global__ void k_pass3(const int* __restrict__ batch, float* __restrict__ out) {
    int i = blockIdx.x * blockDim.x + threadIdx.x;
    if (i < NN) atomicAdd(&out[batch[i]], g_nodeout[i]);
}

extern "C" void kernel_launch(void* const* d_in, const int* in_sizes, int n_in,
                              void* d_out, int out_size) {
    const float* pos   = (const float*)d_in[0];
    const float* x     = (const float*)d_in[1];
    const float* ea    = (const float*)d_in[2];
    const int*   ei    = (const int*)d_in[3];
    const int*   batch = (const int*)d_in[4];
    const float* W1    = (const float*)d_in[5];
    const float* W2    = (const float*)d_in[6];
    const float* W3    = (const float*)d_in[7];
    const float* V1    = (const float*)d_in[8];
    const float* V2    = (const float*)d_in[9];
    const float* V3    = (const float*)d_in[10];
    float* out = (float*)d_out;

    k_zero<<<4224, 1024>>>(out);
    k_pass1a<<<NE / 256, 128>>>(x, ea, ei, W1);
    k_pass1b<<<NE / 256, 128>>>(pos, x, ea, ei, W2, W3);
    k_nodeV<<<(NN * 64 + 255) / 256, 256>>>(V1, V2, V3);
    k_pass2<<<NE / 128, 128>>>(pos, ea, ei);
    k_pass3<<<(NN + 255) / 256, 256>>>(batch, out);
}

// round 3
// speedup vs baseline: 2.2547x; 1.0458x over previous
#include <cuda_runtime.h>

#define NN 20000
#define NE 320000
#define NG 256
#define NA 23
#define NB 7
#define M0 64
#define M1 24
#define M2 16
#define MTOT 104         // 64 + 24 + 16
#define YDIM 728         // 7 * 104
#define NFEAT 216        // 64 + 24*3 + 16*5
#define OFF1 64
#define OFF2 136
#define MDIM 64

__device__ __align__(16) float g_y[(size_t)NN * YDIM];      // 58.2 MB
__device__ __align__(16) float g_nfeat[(size_t)NN * NFEAT]; // 17.3 MB
__device__ __align__(16) float g_m[(size_t)NN * MDIM];
__device__ float g_nodeout[NN];

#define A1  0.078811041f   // 1/sqrt(23*7)
#define C0  0.047245559f   // 1/sqrt(64*7)
#define C1  0.044543540f   // 1/sqrt(24*7*3)
#define C2  0.042257713f   // 1/sqrt(16*7*5)
#define S3  1.7320508075688772f
#define S5  2.23606797749979f
#define S15 3.872983346207417f

#define RED4(p,a,b,c,d) asm volatile("red.global.add.v4.f32 [%0], {%1,%2,%3,%4};" :: "l"(p), "f"(a), "f"(b), "f"(c), "f"(d) : "memory")

__global__ void k_zero(float* __restrict__ out) {
    long long i = (long long)blockIdx.x * blockDim.x + threadIdx.x;
    long long stride = (long long)gridDim.x * blockDim.x;
    for (long long j = i; j < (long long)NN * NFEAT; j += stride) g_nfeat[j] = 0.f;
    for (long long j = i; j < NN; j += stride) g_nodeout[j] = 0.f;
    for (long long j = i; j < NG; j += stride) out[j] = 0.f;
}

// -------- nodeY_a: y[n, v, 0:64] = sum_u x[n,u] * W1[u,v,:] -----------------
__global__ void __launch_bounds__(448) k_nodeY_a(
    const float* __restrict__ x, const float* __restrict__ W1)
{
    __shared__ float Ws[NA * NB * M0];   // 41216 B
    __shared__ float xs[NA];
    for (int i = threadIdx.x; i < NA * NB * M0; i += 448) Ws[i] = W1[i];

    int v = threadIdx.x / M0;            // 0..6
    int w = threadIdx.x % M0;

    for (int n = blockIdx.x; n < NN; n += gridDim.x) {
        __syncthreads();
        if (threadIdx.x < NA) xs[threadIdx.x] = x[n * NA + threadIdx.x];
        __syncthreads();
        float r = 0.f;
#pragma unroll
        for (int u = 0; u < NA; u++)
            r = fmaf(xs[u], Ws[u * (NB * M0) + v * M0 + w], r);
        g_y[(long long)n * YDIM + v * MTOT + w] = r;
    }
}

// -------- nodeY_b: y[n, v, 64:104] from W2 (24) and W3 (16) -----------------
__global__ void __launch_bounds__(320) k_nodeY_b(
    const float* __restrict__ x, const float* __restrict__ W2,
    const float* __restrict__ W3)
{
    __shared__ float Ws[NA * NB * 40];   // 25760 B, per (u,v): [0..23]=W2, [24..39]=W3
    __shared__ float xs[NA];
    for (int i = threadIdx.x; i < NA * NB * M1; i += 320) {
        int p = i / M1, j = i - p * M1;
        Ws[p * 40 + j] = W2[i];
    }
    for (int i = threadIdx.x; i < NA * NB * M2; i += 320) {
        int p = i / M2, j = i - p * M2;
        Ws[p * 40 + M1 + j] = W3[i];
    }

    int v = threadIdx.x / 40;            // 0..6 (tid < 280)
    int j = threadIdx.x % 40;
    bool active = threadIdx.x < 280;

    for (int n = blockIdx.x; n < NN; n += gridDim.x) {
        __syncthreads();
        if (threadIdx.x < NA) xs[threadIdx.x] = x[n * NA + threadIdx.x];
        __syncthreads();
        if (!active) continue;
        float r = 0.f;
#pragma unroll
        for (int u = 0; u < NA; u++)
            r = fmaf(xs[u], Ws[u * (NB * 40) + v * 40 + j], r);
        g_y[(long long)n * YDIM + v * MTOT + 64 + j] = r;
    }
}

// -------- edge1a: n0 scatter (64 features) ----------------------------------
__global__ void __launch_bounds__(128) k_edge1a(
    const float* __restrict__ ea, const int* __restrict__ ei)
{
    int e = blockIdx.x * 128 + threadIdx.x;
    if (e >= NE) return;
    int src = ei[e];
    int dst = ei[NE + e];

    float4 acc[16];
#pragma unroll
    for (int i = 0; i < 16; i++) acc[i] = make_float4(0.f, 0.f, 0.f, 0.f);

    const float* yrow = g_y + (long long)src * YDIM;
#pragma unroll
    for (int v = 0; v < NB; v++) {
        float eav = __ldg(ea + e * NB + v);
        const float4* yp = (const float4*)(yrow + v * MTOT);
#pragma unroll
        for (int i = 0; i < 16; i++) {
            float4 yv = __ldg(yp + i);
            acc[i].x = fmaf(eav, yv.x, acc[i].x);
            acc[i].y = fmaf(eav, yv.y, acc[i].y);
            acc[i].z = fmaf(eav, yv.z, acc[i].z);
            acc[i].w = fmaf(eav, yv.w, acc[i].w);
        }
    }

    float* nf = g_nfeat + (long long)dst * NFEAT;
#pragma unroll
    for (int i = 0; i < 16; i++)
        RED4(nf + i * 4, A1 * acc[i].x, A1 * acc[i].y, A1 * acc[i].z, A1 * acc[i].w);
}

// -------- edge1b: h1 (24) -> l=1 block, h2 (16) -> l=2 block ----------------
__global__ void __launch_bounds__(128) k_edge1b(
    const float* __restrict__ pos, const float* __restrict__ ea,
    const int* __restrict__ ei)
{
    int e = blockIdx.x * 128 + threadIdx.x;
    if (e >= NE) return;
    int src = ei[e];
    int dst = ei[NE + e];

    float4 acc[10];
#pragma unroll
    for (int i = 0; i < 10; i++) acc[i] = make_float4(0.f, 0.f, 0.f, 0.f);

    const float* yrow = g_y + (long long)src * YDIM + 64;
#pragma unroll
    for (int v = 0; v < NB; v++) {
        float eav = __ldg(ea + e * NB + v);
        const float4* yp = (const float4*)(yrow + v * MTOT);
#pragma unroll
        for (int i = 0; i < 10; i++) {
            float4 yv = __ldg(yp + i);
            acc[i].x = fmaf(eav, yv.x, acc[i].x);
            acc[i].y = fmaf(eav, yv.y, acc[i].y);
            acc[i].z = fmaf(eav, yv.z, acc[i].z);
            acc[i].w = fmaf(eav, yv.w, acc[i].w);
        }
    }

    float h[40];
#pragma unroll
    for (int i = 0; i < 10; i++) {
        h[4*i+0] = A1 * acc[i].x;
        h[4*i+1] = A1 * acc[i].y;
        h[4*i+2] = A1 * acc[i].z;
        h[4*i+3] = A1 * acc[i].w;
    }

    float px = pos[src*3+0] - pos[dst*3+0];
    float py = pos[src*3+1] - pos[dst*3+1];
    float pz = pos[src*3+2] - pos[dst*3+2];
    float shv[3] = { S3*px, S3*py, S3*pz };
    float r2 = px*px + py*py + pz*pz;
    float sh2v[5] = { S15*px*py, S15*py*pz, 0.5f*S5*(3.f*pz*pz - r2),
                      S15*px*pz, 0.5f*S15*(px*px - py*py) };

    float* nf = g_nfeat + (long long)dst * NFEAT;
    // l=1: 72 floats, val[k] = h[k/3] * shv[k%3]
#pragma unroll
    for (int q = 0; q < 18; q++) {
        float v0 = h[(4*q+0)/3] * shv[(4*q+0)%3];
        float v1 = h[(4*q+1)/3] * shv[(4*q+1)%3];
        float v2 = h[(4*q+2)/3] * shv[(4*q+2)%3];
        float v3 = h[(4*q+3)/3] * shv[(4*q+3)%3];
        RED4(nf + OFF1 + 4*q, v0, v1, v2, v3);
    }
    // l=2: 80 floats, val[k] = h[24 + k/5] * sh2v[k%5]
#pragma unroll
    for (int q = 0; q < 20; q++) {
        float v0 = h[M1 + (4*q+0)/5] * sh2v[(4*q+0)%5];
        float v1 = h[M1 + (4*q+1)/5] * sh2v[(4*q+1)%5];
        float v2 = h[M1 + (4*q+2)/5] * sh2v[(4*q+2)%5];
        float v3 = h[M1 + (4*q+3)/5] * sh2v[(4*q+3)%5];
        RED4(nf + OFF2 + 4*q, v0, v1, v2, v3);
    }
}

// -------- per-node V contraction: m[node, 63] --------------------------------
__global__ void __launch_bounds__(256) k_nodeV(
    const float* __restrict__ V1, const float* __restrict__ V2,
    const float* __restrict__ V3)
{
    __shared__ float Vs[(M0 + M1 + M2) * NB];
    for (int i = threadIdx.x; i < (M0 + M1 + M2) * NB; i += blockDim.x) {
        float v;
        if (i < M0 * NB)             v = V1[i];
        else if (i < (M0 + M1) * NB) v = V2[i - M0 * NB];
        else                         v = V3[i - (M0 + M1) * NB];
        Vs[i] = v;
    }
    __syncthreads();

    int gid = blockIdx.x * 256 + threadIdx.x;
    int node = gid >> 6;
    int k = gid & 63;
    if (node >= NN) return;
    const float* nf = g_nfeat + (long long)node * NFEAT;

    float r = 0.f;
    if (k < 7) {
        int v = k;
        for (int u = 0; u < M0; u++) r = fmaf(nf[u], Vs[u*NB + v], r);
        r *= C0;
    } else if (k < 28) {
        int t = k - 7; int v = t / 3; int m = t - 3*v;
        for (int u = 0; u < M1; u++) r = fmaf(nf[OFF1 + u*3 + m], Vs[M0*NB + u*NB + v], r);
        r *= C1;
    } else if (k < 63) {
        int t = k - 28; int v = t / 5; int m = t - 5*v;
        for (int u = 0; u < M2; u++) r = fmaf(nf[OFF2 + u*5 + m], Vs[(M0+M1)*NB + u*NB + v], r);
        r *= C2;
    }
    g_m[(long long)node * MDIM + k] = r;
}

// -------- pass 2: per-edge invariant from reduced features ------------------
__global__ void __launch_bounds__(128) k_pass2(
    const float* __restrict__ pos, const float* __restrict__ ea,
    const int* __restrict__ ei)
{
    int e = blockIdx.x * blockDim.x + threadIdx.x;
    if (e >= NE) return;
    int src = ei[e];
    int dst = ei[NE + e];

    float px = pos[src*3+0] - pos[dst*3+0];
    float py = pos[src*3+1] - pos[dst*3+1];
    float pz = pos[src*3+2] - pos[dst*3+2];
    float sh1x = S3*px, sh1y = S3*py, sh1z = S3*pz;
    float r2 = px*px + py*py + pz*pz;
    float sh2_0 = S15*px*py;
    float sh2_1 = S15*py*pz;
    float sh2_2 = 0.5f*S5*(3.f*pz*pz - r2);
    float sh2_3 = S15*px*pz;
    float sh2_4 = 0.5f*S15*(px*px - py*py);

    float eav[NB];
#pragma unroll
    for (int v = 0; v < NB; v++) eav[v] = ea[e * NB + v];

    float mreg[64];
    const float4* mp = (const float4*)(g_m + (long long)src * MDIM);
#pragma unroll
    for (int i = 0; i < 16; i++) ((float4*)mreg)[i] = __ldg(mp + i);

    float g = 0.f;
#pragma unroll
    for (int v = 0; v < NB; v++) {
        const float* m1v = mreg + 7 + v*3;
        const float* m2v = mreg + 28 + v*5;
        float t = mreg[v];
        t = fmaf(sh1x, m1v[0], t);
        t = fmaf(sh1y, m1v[1], t);
        t = fmaf(sh1z, m1v[2], t);
        t = fmaf(sh2_0, m2v[0], t);
        t = fmaf(sh2_1, m2v[1], t);
        t = fmaf(sh2_2, m2v[2], t);
        t = fmaf(sh2_3, m2v[3], t);
        t = fmaf(sh2_4, m2v[4], t);
        g = fmaf(eav[v], t, g);
    }
    atomicAdd(&g_nodeout[dst], g);
}

// -------- pass 3: node -> graph ---------------------------------------------
__global__ void k_pass3(const int* __restrict__ batch, float* __restrict__ out) {
    int i = blockIdx.x * blockDim.x + threadIdx.x;
    if (i < NN) atomicAdd(&out[batch[i]], g_nodeout[i]);
}

extern "C" void kernel_launch(void* const* d_in, const int* in_sizes, int n_in,
                              void* d_out, int out_size) {
    const float* pos   = (const float*)d_in[0];
    const float* x     = (const float*)d_in[1];
    const float* ea    = (const float*)d_in[2];
    const int*   ei    = (const int*)d_in[3];
    const int*   batch = (const int*)d_in[4];
    const float* W1    = (const float*)d_in[5];
    const float* W2    = (const float*)d_in[6];
    const float* W3    = (const float*)d_in[7];
    const float* V1    = (const float*)d_in[8];
    const float* V2    = (const float*)d_in[9];
    const float* V3    = (const float*)d_in[10];
    float* out = (float*)d_out;

    k_zero<<<4224, 1024>>>(out);
    k_nodeY_a<<<592, 448>>>(x, W1);
    k_nodeY_b<<<592, 320>>>(x, W2, W3);
    k_edge1a<<<NE / 128, 128>>>(ea, ei);
    k_edge1b<<<NE / 128, 128>>>(pos, ea, ei);
    k_nodeV<<<(NN * 64 + 255) / 256, 256>>>(V1, V2, V3);
    k_pass2<<<NE / 128, 128>>>(pos, ea, ei);
    k_pass3<<<(NN + 255) / 256, 256>>>(batch, out);
}

// round 4
// speedup vs baseline: 3.0969x; 1.3736x over previous
#include <cuda_runtime.h>

#define NN 20000
#define NE 320000
#define NG 256
#define NA 23
#define NB 7
#define M0 64
#define M1 24
#define M2 16
#define MTOT 104         // 64 + 24 + 16
#define YDIM 728         // 7 * 104
#define NFEAT 216        // 64 + 24*3 + 16*5
#define OFF1 64
#define OFF2 136
#define MDIM 64

__device__ __align__(16) float g_y[(size_t)NN * YDIM];
__device__ __align__(16) float g_nfeat[(size_t)NN * NFEAT];
__device__ __align__(16) float g_m[(size_t)NN * MDIM];
__device__ float g_nodeout[NN];
__device__ int g_cnt[NN];
__device__ int g_cur[NN];
__device__ int g_perm[NE];
__device__ int g_psrc[NE];
__device__ int g_pdst[NE];

#define A1  0.078811041f
#define C0  0.047245559f
#define C1  0.044543540f
#define C2  0.042257713f
#define S3  1.7320508075688772f
#define S5  2.23606797749979f
#define S15 3.872983346207417f

#define RED4(p,a,b,c,d) asm volatile("red.global.add.v4.f32 [%0], {%1,%2,%3,%4};" :: "l"(p), "f"(a), "f"(b), "f"(c), "f"(d) : "memory")

__global__ void k_zero(float* __restrict__ out) {
    long long i = (long long)blockIdx.x * blockDim.x + threadIdx.x;
    long long stride = (long long)gridDim.x * blockDim.x;
    for (long long j = i; j < (long long)NN * NFEAT; j += stride) g_nfeat[j] = 0.f;
    for (long long j = i; j < NN; j += stride) { g_nodeout[j] = 0.f; g_cnt[j] = 0; }
    for (long long j = i; j < NG; j += stride) out[j] = 0.f;
}

// -------- bucketing by src ---------------------------------------------------
__global__ void k_count(const int* __restrict__ ei) {
    int e = blockIdx.x * blockDim.x + threadIdx.x;
    if (e < NE) atomicAdd(&g_cnt[ei[e]], 1);
}

__global__ void __launch_bounds__(1024) k_scan() {   // single block
    __shared__ int sums[1024];
    int t = threadIdx.x;
    int base = t * 20;
    int local[20];
    int s = 0;
#pragma unroll
    for (int i = 0; i < 20; i++) {
        int idx = base + i;
        int c = (idx < NN) ? g_cnt[idx] : 0;
        local[i] = s;
        s += c;
    }
    sums[t] = s;
    __syncthreads();
    for (int d = 1; d < 1024; d <<= 1) {
        int v = (t >= d) ? sums[t - d] : 0;
        __syncthreads();
        if (t >= d) sums[t] += v;
        __syncthreads();
    }
    int excl = (t == 0) ? 0 : sums[t - 1];
#pragma unroll
    for (int i = 0; i < 20; i++) {
        int idx = base + i;
        if (idx < NN) g_cur[idx] = excl + local[i];
    }
}

__global__ void k_fill(const int* __restrict__ ei) {
    int e = blockIdx.x * blockDim.x + threadIdx.x;
    if (e >= NE) return;
    int src = ei[e];
    int p = atomicAdd(&g_cur[src], 1);
    g_perm[p] = e;
    g_psrc[p] = src;
    g_pdst[p] = ei[NE + e];
}

// -------- nodeY_a: y[n, v, 0:64] = sum_u x[n,u] * W1[u,v,:] ------------------
__global__ void __launch_bounds__(448) k_nodeY_a(
    const float* __restrict__ x, const float* __restrict__ W1)
{
    __shared__ float xs[NA];
    int v = threadIdx.x / M0;
    int w = threadIdx.x % M0;
    float wreg[NA];
#pragma unroll
    for (int u = 0; u < NA; u++) wreg[u] = W1[u * 448 + threadIdx.x];

    for (int n = blockIdx.x; n < NN; n += gridDim.x) {
        __syncthreads();
        if (threadIdx.x < NA) xs[threadIdx.x] = x[n * NA + threadIdx.x];
        __syncthreads();
        float r = 0.f;
#pragma unroll
        for (int u = 0; u < NA; u++) r = fmaf(xs[u], wreg[u], r);
        g_y[(long long)n * YDIM + v * MTOT + w] = r;
    }
}

// -------- nodeY_b: y[n, v, 64:104] from W2 / W3 ------------------------------
__global__ void __launch_bounds__(320) k_nodeY_b(
    const float* __restrict__ x, const float* __restrict__ W2,
    const float* __restrict__ W3)
{
    __shared__ float xs[NA];
    bool active = threadIdx.x < 280;
    int v = threadIdx.x / 40;
    int j = threadIdx.x % 40;
    float wreg[NA];
    if (active) {
#pragma unroll
        for (int u = 0; u < NA; u++)
            wreg[u] = (j < M1) ? W2[(u * NB + v) * M1 + j]
                               : W3[(u * NB + v) * M2 + (j - M1)];
    }
    for (int n = blockIdx.x; n < NN; n += gridDim.x) {
        __syncthreads();
        if (threadIdx.x < NA) xs[threadIdx.x] = x[n * NA + threadIdx.x];
        __syncthreads();
        if (!active) continue;
        float r = 0.f;
#pragma unroll
        for (int u = 0; u < NA; u++) r = fmaf(xs[u], wreg[u], r);
        g_y[(long long)n * YDIM + v * MTOT + 64 + j] = r;
    }
}

// -------- edge1a: n0 scatter, 2 threads per edge (32 features each) ----------
__global__ void __launch_bounds__(256) k_edge1a(const float* __restrict__ ea)
{
    int gid = blockIdx.x * 256 + threadIdx.x;
    int p = gid >> 1;
    int half = gid & 1;
    if (p >= NE) return;
    int e = g_perm[p];
    int src = g_psrc[p];
    int dst = g_pdst[p];

    float4 acc[8];
#pragma unroll
    for (int i = 0; i < 8; i++) acc[i] = make_float4(0.f, 0.f, 0.f, 0.f);

    const float* yrow = g_y + (long long)src * YDIM + half * 32;
#pragma unroll
    for (int v = 0; v < NB; v++) {
        float eav = __ldg(ea + e * NB + v);
        const float4* yp = (const float4*)(yrow + v * MTOT);
#pragma unroll
        for (int i = 0; i < 8; i++) {
            float4 yv = __ldg(yp + i);
            acc[i].x = fmaf(eav, yv.x, acc[i].x);
            acc[i].y = fmaf(eav, yv.y, acc[i].y);
            acc[i].z = fmaf(eav, yv.z, acc[i].z);
            acc[i].w = fmaf(eav, yv.w, acc[i].w);
        }
    }

    float* nf = g_nfeat + (long long)dst * NFEAT + half * 32;
#pragma unroll
    for (int i = 0; i < 8; i++)
        RED4(nf + i * 4, A1 * acc[i].x, A1 * acc[i].y, A1 * acc[i].z, A1 * acc[i].w);
}

// -------- edge1b: 2 threads per edge: half0 = l=1 (24), half1 = l=2 (16) -----
__global__ void __launch_bounds__(256) k_edge1b(
    const float* __restrict__ pos, const float* __restrict__ ea)
{
    int gid = blockIdx.x * 256 + threadIdx.x;
    int p = gid >> 1;
    int half = gid & 1;
    if (p >= NE) return;
    int e = g_perm[p];
    int src = g_psrc[p];
    int dst = g_pdst[p];

    float px = pos[src*3+0] - pos[dst*3+0];
    float py = pos[src*3+1] - pos[dst*3+1];
    float pz = pos[src*3+2] - pos[dst*3+2];

    if (half == 0) {
        // l=1: h[0..23] from y[64..87]
        float4 acc[6];
#pragma unroll
        for (int i = 0; i < 6; i++) acc[i] = make_float4(0.f,0.f,0.f,0.f);
        const float* yrow = g_y + (long long)src * YDIM + 64;
#pragma unroll
        for (int v = 0; v < NB; v++) {
            float eav = __ldg(ea + e * NB + v);
            const float4* yp = (const float4*)(yrow + v * MTOT);
#pragma unroll
            for (int i = 0; i < 6; i++) {
                float4 yv = __ldg(yp + i);
                acc[i].x = fmaf(eav, yv.x, acc[i].x);
                acc[i].y = fmaf(eav, yv.y, acc[i].y);
                acc[i].z = fmaf(eav, yv.z, acc[i].z);
                acc[i].w = fmaf(eav, yv.w, acc[i].w);
            }
        }
        float h[24];
#pragma unroll
        for (int i = 0; i < 6; i++) {
            h[4*i+0] = A1*acc[i].x; h[4*i+1] = A1*acc[i].y;
            h[4*i+2] = A1*acc[i].z; h[4*i+3] = A1*acc[i].w;
        }
        float shv[3] = { S3*px, S3*py, S3*pz };
        float* nf = g_nfeat + (long long)dst * NFEAT;
#pragma unroll
        for (int q = 0; q < 18; q++) {
            float v0 = h[(4*q+0)/3] * shv[(4*q+0)%3];
            float v1 = h[(4*q+1)/3] * shv[(4*q+1)%3];
            float v2 = h[(4*q+2)/3] * shv[(4*q+2)%3];
            float v3 = h[(4*q+3)/3] * shv[(4*q+3)%3];
            RED4(nf + OFF1 + 4*q, v0, v1, v2, v3);
        }
    } else {
        // l=2: h[0..15] from y[88..103]
        float4 acc[4];
#pragma unroll
        for (int i = 0; i < 4; i++) acc[i] = make_float4(0.f,0.f,0.f,0.f);
        const float* yrow = g_y + (long long)src * YDIM + 88;
#pragma unroll
        for (int v = 0; v < NB; v++) {
            float eav = __ldg(ea + e * NB + v);
            const float4* yp = (const float4*)(yrow + v * MTOT);
#pragma unroll
            for (int i = 0; i < 4; i++) {
                float4 yv = __ldg(yp + i);
                acc[i].x = fmaf(eav, yv.x, acc[i].x);
                acc[i].y = fmaf(eav, yv.y, acc[i].y);
                acc[i].z = fmaf(eav, yv.z, acc[i].z);
                acc[i].w = fmaf(eav, yv.w, acc[i].w);
            }
        }
        float h[16];
#pragma unroll
        for (int i = 0; i < 4; i++) {
            h[4*i+0] = A1*acc[i].x; h[4*i+1] = A1*acc[i].y;
            h[4*i+2] = A1*acc[i].z; h[4*i+3] = A1*acc[i].w;
        }
        float r2 = px*px + py*py + pz*pz;
        float sh2v[5] = { S15*px*py, S15*py*pz, 0.5f*S5*(3.f*pz*pz - r2),
                          S15*px*pz, 0.5f*S15*(px*px - py*py) };
        float* nf = g_nfeat + (long long)dst * NFEAT;
#pragma unroll
        for (int q = 0; q < 20; q++) {
            float v0 = h[(4*q+0)/5] * sh2v[(4*q+0)%5];
            float v1 = h[(4*q+1)/5] * sh2v[(4*q+1)%5];
            float v2 = h[(4*q+2)/5] * sh2v[(4*q+2)%5];
            float v3 = h[(4*q+3)/5] * sh2v[(4*q+3)%5];
            RED4(nf + OFF2 + 4*q, v0, v1, v2, v3);
        }
    }
}

// -------- per-node V contraction: m[node, 63] --------------------------------
__global__ void __launch_bounds__(256) k_nodeV(
    const float* __restrict__ V1, const float* __restrict__ V2,
    const float* __restrict__ V3)
{
    __shared__ float Vs[(M0 + M1 + M2) * NB];
    for (int i = threadIdx.x; i < (M0 + M1 + M2) * NB; i += blockDim.x) {
        float v;
        if (i < M0 * NB)             v = V1[i];
        else if (i < (M0 + M1) * NB) v = V2[i - M0 * NB];
        else                         v = V3[i - (M0 + M1) * NB];
        Vs[i] = v;
    }
    __syncthreads();

    int gid = blockIdx.x * 256 + threadIdx.x;
    int node = gid >> 6;
    int k = gid & 63;
    if (node >= NN) return;
    const float* nf = g_nfeat + (long long)node * NFEAT;

    float r = 0.f;
    if (k < 7) {
        int v = k;
        for (int u = 0; u < M0; u++) r = fmaf(nf[u], Vs[u*NB + v], r);
        r *= C0;
    } else if (k < 28) {
        int t = k - 7; int v = t / 3; int m = t - 3*v;
        for (int u = 0; u < M1; u++) r = fmaf(nf[OFF1 + u*3 + m], Vs[M0*NB + u*NB + v], r);
        r *= C1;
    } else if (k < 63) {
        int t = k - 28; int v = t / 5; int m = t - 5*v;
        for (int u = 0; u < M2; u++) r = fmaf(nf[OFF2 + u*5 + m], Vs[(M0+M1)*NB + u*NB + v], r);
        r *= C2;
    }
    g_m[(long long)node * MDIM + k] = r;
}

// -------- pass 2: per-edge invariant, perm-ordered ---------------------------
__global__ void __launch_bounds__(128) k_pass2(
    const float* __restrict__ pos, const float* __restrict__ ea)
{
    int p = blockIdx.x * blockDim.x + threadIdx.x;
    if (p >= NE) return;
    int e = g_perm[p];
    int src = g_psrc[p];
    int dst = g_pdst[p];

    float px = pos[src*3+0] - pos[dst*3+0];
    float py = pos[src*3+1] - pos[dst*3+1];
    float pz = pos[src*3+2] - pos[dst*3+2];
    float sh1x = S3*px, sh1y = S3*py, sh1z = S3*pz;
    float r2 = px*px + py*py + pz*pz;
    float sh2_0 = S15*px*py;
    float sh2_1 = S15*py*pz;
    float sh2_2 = 0.5f*S5*(3.f*pz*pz - r2);
    float sh2_3 = S15*px*pz;
    float sh2_4 = 0.5f*S15*(px*px - py*py);

    float eav[NB];
#pragma unroll
    for (int v = 0; v < NB; v++) eav[v] = __ldg(ea + e * NB + v);

    float mreg[64];
    const float4* mp = (const float4*)(g_m + (long long)src * MDIM);
#pragma unroll
    for (int i = 0; i < 16; i++) ((float4*)mreg)[i] = __ldg(mp + i);

    float g = 0.f;
#pragma unroll
    for (int v = 0; v < NB; v++) {
        const float* m1v = mreg + 7 + v*3;
        const float* m2v = mreg + 28 + v*5;
        float t = mreg[v];
        t = fmaf(sh1x, m1v[0], t);
        t = fmaf(sh1y, m1v[1], t);
        t = fmaf(sh1z, m1v[2], t);
        t = fmaf(sh2_0, m2v[0], t);
        t = fmaf(sh2_1, m2v[1], t);
        t = fmaf(sh2_2, m2v[2], t);
        t = fmaf(sh2_3, m2v[3], t);
        t = fmaf(sh2_4, m2v[4], t);
        g = fmaf(eav[v], t, g);
    }
    atomicAdd(&g_nodeout[dst], g);
}

// -------- pass 3: node -> graph ---------------------------------------------
__global__ void k_pass3(const int* __restrict__ batch, float* __restrict__ out) {
    int i = blockIdx.x * blockDim.x + threadIdx.x;
    if (i < NN) atomicAdd(&out[batch[i]], g_nodeout[i]);
}

extern "C" void kernel_launch(void* const* d_in, const int* in_sizes, int n_in,
                              void* d_out, int out_size) {
    const float* pos   = (const float*)d_in[0];
    const float* x     = (const float*)d_in[1];
    const float* ea    = (const float*)d_in[2];
    const int*   ei    = (const int*)d_in[3];
    const int*   batch = (const int*)d_in[4];
    const float* W1    = (const float*)d_in[5];
    const float* W2    = (const float*)d_in[6];
    const float* W3    = (const float*)d_in[7];
    const float* V1    = (const float*)d_in[8];
    const float* V2    = (const float*)d_in[9];
    const float* V3    = (const float*)d_in[10];
    float* out = (float*)d_out;

    k_zero<<<4224, 1024>>>(out);
    k_count<<<(NE + 255) / 256, 256>>>(ei);
    k_scan<<<1, 1024>>>();
    k_fill<<<(NE + 255) / 256, 256>>>(ei);
    k_nodeY_a<<<1184, 448>>>(x, W1);
    k_nodeY_b<<<1184, 320>>>(x, W2, W3);
    k_edge1a<<<(2 * NE) / 256, 256>>>(ea);
    k_edge1b<<<(2 * NE) / 256, 256>>>(pos, ea);
    k_nodeV<<<(NN * 64 + 255) / 256, 256>>>(V1, V2, V3);
    k_pass2<<<(NE + 127) / 128, 128>>>(pos, ea);
    k_pass3<<<(NN + 255) / 256, 256>>>(batch, out);
}